// round 14
// baseline (speedup 1.0000x reference)
#include <cuda_runtime.h>
#include <cuda_bf16.h>
#include <math.h>
#include <stdint.h>

#define N_NODES   100000
#define N_EDGES   400000
#define IN_DIM    100
#define D         200
#define NUM_STEPS 4

#define NODES_PAD  100096         // 256 | 100096
#define MT256      391            // NODES_PAD / 256
#define KPART      224
#define KEFF       672            // [A_hi | A_hi | A_lo] x [B_hi ; B_lo ; B_hi]
#define NCH        21             // KEFF / 32
#define NCHUNK     84             // KEFF / 8
#define NT1        7
#define N1_PAD     896
#define NT2        5
#define N2_PAD     640

// ---------------- device scratch ----------------
__device__ float g_h[N_NODES * D];
__device__ float g_T[(size_t)NODES_PAD * N1_PAD];           // [m | gh | pad]
__device__ float g_gi[(size_t)NODES_PAD * N2_PAD];
__device__ __align__(16) __nv_bfloat16 g_Ah[(size_t)NODES_PAD * KEFF];
__device__ __align__(16) __nv_bfloat16 g_Aa[(size_t)NODES_PAD * KEFF];
__device__ __align__(16) __nv_bfloat16 g_B1e[(size_t)NUM_STEPS * KEFF * N1_PAD];
__device__ __align__(16) __nv_bfloat16 g_B2e[(size_t)KEFF * N2_PAD];
__device__ float g_bias1[N1_PAD];
__device__ float g_bias2[N2_PAD];
__device__ float g_pool[D];
__device__ int   g_is64;
__device__ int   g_cnt[N_NODES];
__device__ int   g_row[N_NODES + 1];
__device__ int   g_cur[N_NODES];
__device__ int   g_csr[N_EDGES];

// ---------------- PTX helpers ----------------
__device__ __forceinline__ uint32_t saddr(const void* p) {
    uint32_t a;
    asm("{ .reg .u64 t; cvta.to.shared.u64 t, %1; cvt.u32.u64 %0, t; }" : "=r"(a) : "l"(p));
    return a;
}
#define CP_ASYNC16(dst, src) \
    asm volatile("cp.async.cg.shared.global [%0], [%1], 16;" :: "r"(dst), "l"(src))
#define CP_COMMIT() asm volatile("cp.async.commit_group;")

__device__ __forceinline__ void ldsm4(uint32_t* r, uint32_t a) {
    asm volatile("ldmatrix.sync.aligned.m8n8.x4.shared.b16 {%0,%1,%2,%3}, [%4];"
        : "=r"(r[0]), "=r"(r[1]), "=r"(r[2]), "=r"(r[3]) : "r"(a));
}
__device__ __forceinline__ void ldsm4t(uint32_t* r, uint32_t a) {
    asm volatile("ldmatrix.sync.aligned.m8n8.x4.trans.shared.b16 {%0,%1,%2,%3}, [%4];"
        : "=r"(r[0]), "=r"(r[1]), "=r"(r[2]), "=r"(r[3]) : "r"(a));
}
__device__ __forceinline__ void mma16816(float* c, const uint32_t* a, uint32_t b0, uint32_t b1) {
    asm volatile("mma.sync.aligned.m16n8k16.row.col.f32.bf16.bf16.f32 "
        "{%0,%1,%2,%3}, {%4,%5,%6,%7}, {%8,%9}, {%0,%1,%2,%3};"
        : "+f"(c[0]), "+f"(c[1]), "+f"(c[2]), "+f"(c[3])
        : "r"(a[0]), "r"(a[1]), "r"(a[2]), "r"(a[3]), "r"(b0), "r"(b1));
}

// ---------------- prep: all weight images + biases ----------------
__global__ void prep_w(const float* __restrict__ W, const float* __restrict__ w_hh,
                       const float* __restrict__ w_ih,
                       const float* __restrict__ b_hh, const float* __restrict__ b_ih) {
    const int T1 = NUM_STEPS * KEFF * (N1_PAD / 8);
    const int T2 = KEFF * (N2_PAD / 8);
    int t = blockIdx.x * blockDim.x + threadIdx.x;
    if (t < T1) {
        int c8 = t % (N1_PAD / 8); int x = t / (N1_PAD / 8);
        int k = x % KEFF; int s = x / KEFF;
        int part = k / KPART, kk = k % KPART;
        int j0 = c8 * 8;
        __nv_bfloat16 out[8];
#pragma unroll
        for (int j = 0; j < 8; j++) {
            int col = j0 + j;
            float v = 0.f;
            if (kk < D && col < 4 * D)
                v = (col < D) ? W[(size_t)s * D * D + kk * D + col]
                              : w_hh[(size_t)(col - D) * D + kk];
            __nv_bfloat16 hi = __float2bfloat16_rn(v);
            out[j] = (part == 1) ? __float2bfloat16_rn(v - __bfloat162float(hi)) : hi;
        }
        *(uint4*)(g_B1e + ((size_t)(s * KEFF + k)) * N1_PAD + j0) = *(uint4*)out;
    } else if (t < T1 + T2) {
        int u = t - T1;
        int c8 = u % (N2_PAD / 8); int k = u / (N2_PAD / 8);
        int part = k / KPART, kk = k % KPART;
        int j0 = c8 * 8;
        __nv_bfloat16 out[8];
#pragma unroll
        for (int j = 0; j < 8; j++) {
            int col = j0 + j;
            float v = (kk < D && col < 3 * D) ? w_ih[(size_t)col * D + kk] : 0.f;
            __nv_bfloat16 hi = __float2bfloat16_rn(v);
            out[j] = (part == 1) ? __float2bfloat16_rn(v - __bfloat162float(hi)) : hi;
        }
        *(uint4*)(g_B2e + (size_t)k * N2_PAD + j0) = *(uint4*)out;
    } else {
        int u = t - T1 - T2;
        if (u < N1_PAD) g_bias1[u] = (u >= D && u < 4 * D) ? b_hh[u - D] : 0.f;
        else if (u < N1_PAD + N2_PAD) {
            int v = u - N1_PAD;
            g_bias2[v] = (v < 3 * D) ? b_ih[v] : 0.f;
        }
    }
}

// ---------------- dtype detect + zero CSR counters ----------------
__global__ void detect_zero(const int* __restrict__ ei32) {
    int t = blockIdx.x * blockDim.x + threadIdx.x;
    if (t < N_NODES) g_cnt[t] = 0;
    if (blockIdx.x == 0) {
        __shared__ int ok;
        if (threadIdx.x == 0) ok = 1;
        __syncthreads();
        if (ei32[2 * threadIdx.x + 1] != 0) ok = 0;
        __syncthreads();
        if (threadIdx.x == 0) g_is64 = ok;
    }
}

// ---------------- init: h = pad(x), + bf16 image, + pad-row zeros ----------------
__global__ __launch_bounds__(256) void init_fused(const float* __restrict__ x) {
    __shared__ float hs[8][KPART];
    int warp = threadIdx.x >> 5, lane = threadIdx.x & 31;
    int n = blockIdx.x * 8 + warp;
    if (n >= NODES_PAD) return;
    if (n < N_NODES) {
        for (int j = lane; j < KPART; j += 32) {
            float v = (j < IN_DIM) ? x[(size_t)n * IN_DIM + j] : 0.f;
            if (j < D) g_h[(size_t)n * D + j] = v;
            hs[warp][j] = (j < D) ? v : 0.f;
        }
        __syncwarp();
        for (int c = lane; c < NCHUNK; c += 32) {
            int j0 = c * 8;
            int part = j0 / KPART, kk0 = j0 % KPART;
            __nv_bfloat16 out[8];
#pragma unroll
            for (int q = 0; q < 8; q++) {
                float v = hs[warp][kk0 + q];
                __nv_bfloat16 hi = __float2bfloat16_rn(v);
                out[q] = (part < 2) ? hi : __float2bfloat16_rn(v - __bfloat162float(hi));
            }
            *(uint4*)(g_Ah + (size_t)n * KEFF + j0) = *(uint4*)out;
        }
    } else {
        for (int c = lane; c < NCHUNK; c += 32) {
            *(uint4*)(g_Ah + (size_t)n * KEFF + c * 8) = make_uint4(0, 0, 0, 0);
            *(uint4*)(g_Aa + (size_t)n * KEFF + c * 8) = make_uint4(0, 0, 0, 0);
        }
    }
}

// ---------------- CSR build (range-clamped) ----------------
__global__ void csr_count(const void* __restrict__ eiv) {
    int e = blockIdx.x * blockDim.x + threadIdx.x;
    if (e >= N_EDGES) return;
    int src, dst;
    if (g_is64) {
        const long long* ei = (const long long*)eiv;
        src = (int)ei[e]; dst = (int)ei[N_EDGES + e];
    } else {
        const int* ei = (const int*)eiv;
        src = ei[e]; dst = ei[N_EDGES + e];
    }
    if ((unsigned)src >= N_NODES || (unsigned)dst >= N_NODES) return;
    atomicAdd(&g_cnt[dst], 1);
}

__global__ void csr_scan() {     // single block, 1024 threads
    __shared__ int tsum[1024];
    int tid = threadIdx.x;
    const int CHK = (N_NODES + 1023) / 1024;
    int lo = tid * CHK;
    int hi = lo + CHK; if (hi > N_NODES) hi = N_NODES;
    int s = 0;
    for (int i = lo; i < hi; i++) s += g_cnt[i];
    tsum[tid] = s;
    __syncthreads();
    for (int off = 1; off < 1024; off <<= 1) {
        int v = (tid >= off) ? tsum[tid - off] : 0;
        __syncthreads();
        tsum[tid] += v;
        __syncthreads();
    }
    int excl = (tid == 0) ? 0 : tsum[tid - 1];
    for (int i = lo; i < hi; i++) {
        int c = g_cnt[i];
        g_row[i] = excl;
        g_cur[i] = excl;
        excl += c;
    }
    if (tid == 1023) g_row[N_NODES] = tsum[1023];
}

__global__ void csr_fill(const void* __restrict__ eiv) {
    int e = blockIdx.x * blockDim.x + threadIdx.x;
    if (e >= N_EDGES) return;
    int src, dst;
    if (g_is64) {
        const long long* ei = (const long long*)eiv;
        src = (int)ei[e]; dst = (int)ei[N_EDGES + e];
    } else {
        const int* ei = (const int*)eiv;
        src = ei[e]; dst = ei[N_EDGES + e];
    }
    if ((unsigned)src >= N_NODES || (unsigned)dst >= N_NODES) return;
    int pos = atomicAdd(&g_cur[dst], 1);
    g_csr[pos] = src;
}

// ---------------- HMMA GEMM: CTA 256x128, 8 warps of 64x64, 2-stage ----------------
// smem-BW optimized: 16 MAC/byte of fragment reads (vs 8 at 32x32 warps)
#define APITCH 40
#define BPITCH 136
#define A_STG (256 * APITCH)           // bf16 elems per A stage
#define B_STG (32 * BPITCH)
#define SMEM_GEMM (2 * (A_STG + B_STG) * 2)   // bytes

__global__ __launch_bounds__(256) void gemm_mma(
    const __nv_bfloat16* __restrict__ A,
    const __nv_bfloat16* __restrict__ B,
    const float* __restrict__ bias,
    float* __restrict__ C, int ldb)
{
    extern __shared__ __align__(16) unsigned char smem_raw[];
    __nv_bfloat16 (*As)[256][APITCH] =
        reinterpret_cast<__nv_bfloat16(*)[256][APITCH]>(smem_raw);
    __nv_bfloat16 (*Bs)[32][BPITCH] =
        reinterpret_cast<__nv_bfloat16(*)[32][BPITCH]>(smem_raw + 2 * A_STG * 2);

    const int tid = threadIdx.x, lane = tid & 31, wid = tid >> 5;
    const int warpM = (wid >> 1) * 64, warpN = (wid & 1) * 64;
    const int row0 = blockIdx.y * 256, col0 = blockIdx.x * 128;

    float acc[4][8][4];
#pragma unroll
    for (int i = 0; i < 4; i++)
#pragma unroll
        for (int j = 0; j < 8; j++)
#pragma unroll
            for (int q = 0; q < 4; q++) acc[i][j][q] = 0.f;

#define LOAD_STAGE(ch, buf) do { \
    int _k0 = (ch) * 32; \
    _Pragma("unroll") \
    for (int it = 0; it < 4; it++) { \
        int idx = tid + it * 256; \
        int r = idx >> 2, seg = idx & 3; \
        const void* s_ = A + (size_t)(row0 + r) * KEFF + _k0 + seg * 8; \
        CP_ASYNC16(saddr(&As[buf][r][seg * 8]), s_); \
    } \
    _Pragma("unroll") \
    for (int it = 0; it < 2; it++) { \
        int idx = tid + it * 256; \
        int r = idx >> 4, seg = idx & 15; \
        const void* s_ = B + (size_t)(_k0 + r) * ldb + col0 + seg * 8; \
        CP_ASYNC16(saddr(&Bs[buf][r][seg * 8]), s_); \
    } \
    CP_COMMIT(); \
} while (0)

    LOAD_STAGE(0, 0);

    for (int ch = 0; ch < NCH; ch++) {
        int buf = ch & 1;
        if (ch + 1 < NCH) {
            LOAD_STAGE(ch + 1, buf ^ 1);
            asm volatile("cp.async.wait_group 1;");
        } else {
            asm volatile("cp.async.wait_group 0;");
        }
        __syncthreads();

#pragma unroll
        for (int kk = 0; kk < 2; kk++) {
            uint32_t a[4][4];
#pragma unroll
            for (int mt = 0; mt < 4; mt++)
                ldsm4(a[mt], saddr(&As[buf][warpM + mt * 16 + (lane & 15)][kk * 16 + (lane >> 4) * 8]));
#pragma unroll
            for (int nt = 0; nt < 4; nt++) {
                uint32_t b[4];
                ldsm4t(b, saddr(&Bs[buf][kk * 16 + (lane & 15)][warpN + nt * 16 + (lane >> 4) * 8]));
#pragma unroll
                for (int mt = 0; mt < 4; mt++) {
                    mma16816(acc[mt][nt * 2 + 0], a[mt], b[0], b[1]);
                    mma16816(acc[mt][nt * 2 + 1], a[mt], b[2], b[3]);
                }
            }
        }
        __syncthreads();
    }

#pragma unroll
    for (int mt = 0; mt < 4; mt++) {
        int r = row0 + warpM + mt * 16 + (lane >> 2);
#pragma unroll
        for (int n8 = 0; n8 < 8; n8++) {
            int c = col0 + warpN + n8 * 8 + (lane & 3) * 2;
            float b0 = bias[c], b1 = bias[c + 1];
            float2 v0 = make_float2(acc[mt][n8][0] + b0, acc[mt][n8][1] + b1);
            float2 v1 = make_float2(acc[mt][n8][2] + b0, acc[mt][n8][3] + b1);
            *(float2*)(C + (size_t)r * ldb + c) = v0;
            *(float2*)(C + (size_t)(r + 8) * ldb + c) = v1;
        }
    }
#undef LOAD_STAGE
}

// ---------------- CSR segment-sum (no atomics) ----------------
__global__ __launch_bounds__(256) void aggregate_kernel() {
    __shared__ float acc_s[KPART];
    int n = blockIdx.x;
    int j = threadIdx.x;
    int beg = g_row[n], end = g_row[n + 1];
    if (j < KPART) {
        float acc = 0.f;
        if (j < D) {
            int e = beg;
            for (; e + 1 < end; e += 2) {
                int s0 = g_csr[e], s1 = g_csr[e + 1];
                acc += g_T[(size_t)s0 * N1_PAD + j] + g_T[(size_t)s1 * N1_PAD + j];
            }
            if (e < end) acc += g_T[(size_t)g_csr[e] * N1_PAD + j];
        }
        acc_s[j] = acc;
    }
    __syncthreads();
    if (j < NCHUNK) {
        int j0 = j * 8;
        int part = j0 / KPART, kk0 = j0 % KPART;
        __nv_bfloat16 out[8];
#pragma unroll
        for (int q = 0; q < 8; q++) {
            float v = acc_s[kk0 + q];
            __nv_bfloat16 hi = __float2bfloat16_rn(v);
            out[q] = (part < 2) ? hi : __float2bfloat16_rn(v - __bfloat162float(hi));
        }
        *(uint4*)(g_Aa + (size_t)n * KEFF + j0) = *(uint4*)out;
    }
}

// ---------------- fused GRU: h update + next-step bf16 image ----------------
__global__ __launch_bounds__(256) void gru_kernel() {
    __shared__ float hs[8][KPART];
    int warp = threadIdx.x >> 5, lane = threadIdx.x & 31;
    int n = blockIdx.x * 8 + warp;
    if (n >= N_NODES) return;
    size_t gb = (size_t)n * N2_PAD;
    size_t tb = (size_t)n * N1_PAD;
    for (int j = lane; j < KPART; j += 32) {
        float hnew = 0.f;
        if (j < D) {
            float ir  = g_gi[gb + j];
            float iz  = g_gi[gb + D + j];
            float in_ = g_gi[gb + 2 * D + j];
            float hr  = g_T[tb + D + j];
            float hz  = g_T[tb + 2 * D + j];
            float hn  = g_T[tb + 3 * D + j];
            float r = 1.f / (1.f + expf(-(ir + hr)));
            float z = 1.f / (1.f + expf(-(iz + hz)));
            float nn = tanhf(in_ + r * hn);
            float hold = g_h[(size_t)n * D + j];
            hnew = (1.f - z) * nn + z * hold;
            g_h[(size_t)n * D + j] = hnew;
        }
        hs[warp][j] = hnew;
    }
    __syncwarp();
    for (int c = lane; c < NCHUNK; c += 32) {
        int j0 = c * 8;
        int part = j0 / KPART, kk0 = j0 % KPART;
        __nv_bfloat16 out[8];
#pragma unroll
        for (int q = 0; q < 8; q++) {
            float v = hs[warp][kk0 + q];
            __nv_bfloat16 hi = __float2bfloat16_rn(v);
            out[q] = (part < 2) ? hi : __float2bfloat16_rn(v - __bfloat162float(hi));
        }
        *(uint4*)(g_Ah + (size_t)n * KEFF + j0) = *(uint4*)out;
    }
}

// ---------------- global max pool + classifier ----------------
__global__ void pool_kernel() {
    int j = blockIdx.x;
    float m = -3.402823466e38f;
    for (int n = threadIdx.x; n < N_NODES; n += 256)
        m = fmaxf(m, g_h[(size_t)n * D + j]);
    __shared__ float s[256];
    s[threadIdx.x] = m;
    __syncthreads();
    for (int o = 128; o > 0; o >>= 1) {
        if (threadIdx.x < o) s[threadIdx.x] = fmaxf(s[threadIdx.x], s[threadIdx.x + o]);
        __syncthreads();
    }
    if (threadIdx.x == 0) g_pool[j] = fmaxf(s[0], 0.f);
}

__global__ void cls_kernel(const float* __restrict__ cls_w,
                           const float* __restrict__ cls_b,
                           float* __restrict__ out) {
    if (blockIdx.x == 0 && threadIdx.x == 0) {
        float l0 = cls_b[0], l1 = cls_b[1];
        for (int j = 0; j < D; j++) {
            float p = g_pool[j];
            l0 += p * cls_w[j];
            l1 += p * cls_w[D + j];
        }
        float mx = fmaxf(l0, l1);
        float e0 = expf(l0 - mx), e1 = expf(l1 - mx);
        float s = e0 + e1;
        out[0] = e0 / s;
        out[1] = e1 / s;
    }
}

// ---------------- host launcher ----------------
extern "C" void kernel_launch(void* const* d_in, const int* in_sizes, int n_in,
                              void* d_out, int out_size) {
    const float* x     = (const float*)d_in[0];
    const float* W     = (const float*)d_in[1];
    const float* w_ih  = (const float*)d_in[2];
    const float* w_hh  = (const float*)d_in[3];
    const float* b_ih  = (const float*)d_in[4];
    const float* b_hh  = (const float*)d_in[5];
    const float* cls_w = (const float*)d_in[6];
    const float* cls_b = (const float*)d_in[7];
    const void*  ei    = (const void*)d_in[8];
    float* out = (float*)d_out;

    float *T_p, *gi_p, *b1_p, *b2_p;
    __nv_bfloat16 *Ah_p, *Aa_p, *B1_p, *B2_p;
    cudaGetSymbolAddress((void**)&T_p,  g_T);
    cudaGetSymbolAddress((void**)&gi_p, g_gi);
    cudaGetSymbolAddress((void**)&Ah_p, g_Ah);
    cudaGetSymbolAddress((void**)&Aa_p, g_Aa);
    cudaGetSymbolAddress((void**)&B1_p, g_B1e);
    cudaGetSymbolAddress((void**)&B2_p, g_B2e);
    cudaGetSymbolAddress((void**)&b1_p, g_bias1);
    cudaGetSymbolAddress((void**)&b2_p, g_bias2);

    cudaFuncSetAttribute(gemm_mma, cudaFuncAttributeMaxDynamicSharedMemorySize, SMEM_GEMM);

    const int TB = 256;
    const int PREP_TOTAL = NUM_STEPS * KEFF * (N1_PAD / 8) + KEFF * (N2_PAD / 8) + N1_PAD + N2_PAD;

    prep_w<<<(PREP_TOTAL + TB - 1) / TB, TB>>>(W, w_hh, w_ih, b_hh, b_ih);             // 0
    detect_zero<<<(N_NODES + TB - 1) / TB, TB>>>((const int*)ei);                       // 1
    init_fused<<<(NODES_PAD + 7) / 8, 256>>>(x);                                        // 2

    dim3 grid1(NT1, MT256), grid2(NT2, MT256);
    for (int s = 0; s < NUM_STEPS; s++) {
        gemm_mma<<<grid1, 256, SMEM_GEMM>>>(Ah_p, B1_p + (size_t)s * KEFF * N1_PAD, b1_p, T_p, N1_PAD); // 3
        if (s == 0) {
            csr_count<<<(N_EDGES + TB - 1) / TB, TB>>>(ei);
            csr_scan<<<1, 1024>>>();
            csr_fill<<<(N_EDGES + TB - 1) / TB, TB>>>(ei);
        }
        aggregate_kernel<<<N_NODES, 256>>>();
        gemm_mma<<<grid2, 256, SMEM_GEMM>>>(Aa_p, B2_p, b2_p, gi_p, N2_PAD);
        gru_kernel<<<(N_NODES + 7) / 8, 256>>>();
    }

    pool_kernel<<<D, 256>>>();
    cls_kernel<<<1, 32>>>(cls_w, cls_b, out);
}

// round 15
// speedup vs baseline: 1.9107x; 1.9107x over previous
#include <cuda_runtime.h>
#include <cuda_bf16.h>
#include <math.h>
#include <stdint.h>

#define N_NODES   100000
#define N_EDGES   400000
#define IN_DIM    100
#define D         200
#define NUM_STEPS 4

#define M_TILES    782            // ceil(100000/128)
#define NODES_PAD  (M_TILES*128)  // 100096
#define KPART      224
#define KEFF       672            // [A_hi | A_hi | A_lo] x [B_hi ; B_lo ; B_hi]
#define NCH        21             // KEFF / 32
#define NCHUNK     84             // KEFF / 8
#define NT         5              // N tiles (600 -> 640)
#define NPAD       640

// ---------------- device scratch ----------------
__device__ float g_h[N_NODES * D];
__device__ float g_T[(size_t)NODES_PAD * NPAD];             // gh
__device__ float g_gi[(size_t)NODES_PAD * NPAD];            // gi
__device__ float g_Wc[NUM_STEPS * D * 600];                 // W[i] @ w_ih^T (fp32)
__device__ __align__(16) __nv_bfloat16 g_Ah[(size_t)NODES_PAD * KEFF];   // h image
__device__ __align__(16) __nv_bfloat16 g_As[(size_t)NODES_PAD * KEFF];   // hsum image
__device__ __align__(16) __nv_bfloat16 g_Bgi[(size_t)NUM_STEPS * KEFF * NPAD];  // Wc images
__device__ __align__(16) __nv_bfloat16 g_Bhh[(size_t)KEFF * NPAD];              // w_hh^T image
__device__ float g_bias_hh[NPAD];
__device__ float g_bias_ih[NPAD];
__device__ float g_pool[D];
__device__ int   g_is64;
__device__ int   g_cnt[N_NODES];
__device__ int   g_row[N_NODES + 1];
__device__ int   g_cur[N_NODES];
__device__ int   g_csr[N_EDGES];

// ---------------- PTX helpers ----------------
__device__ __forceinline__ uint32_t saddr(const void* p) {
    uint32_t a;
    asm("{ .reg .u64 t; cvta.to.shared.u64 t, %1; cvt.u32.u64 %0, t; }" : "=r"(a) : "l"(p));
    return a;
}
#define CP_ASYNC16(dst, src) \
    asm volatile("cp.async.cg.shared.global [%0], [%1], 16;" :: "r"(dst), "l"(src))
#define CP_COMMIT() asm volatile("cp.async.commit_group;")

__device__ __forceinline__ void ldsm4(uint32_t* r, uint32_t a) {
    asm volatile("ldmatrix.sync.aligned.m8n8.x4.shared.b16 {%0,%1,%2,%3}, [%4];"
        : "=r"(r[0]), "=r"(r[1]), "=r"(r[2]), "=r"(r[3]) : "r"(a));
}
__device__ __forceinline__ void ldsm4t(uint32_t* r, uint32_t a) {
    asm volatile("ldmatrix.sync.aligned.m8n8.x4.trans.shared.b16 {%0,%1,%2,%3}, [%4];"
        : "=r"(r[0]), "=r"(r[1]), "=r"(r[2]), "=r"(r[3]) : "r"(a));
}
__device__ __forceinline__ void mma16816(float* c, const uint32_t* a, uint32_t b0, uint32_t b1) {
    asm volatile("mma.sync.aligned.m16n8k16.row.col.f32.bf16.bf16.f32 "
        "{%0,%1,%2,%3}, {%4,%5,%6,%7}, {%8,%9}, {%0,%1,%2,%3};"
        : "+f"(c[0]), "+f"(c[1]), "+f"(c[2]), "+f"(c[3])
        : "r"(a[0]), "r"(a[1]), "r"(a[2]), "r"(a[3]), "r"(b0), "r"(b1));
}

// ---------------- prep_wc: Wc[s] = W[s] @ w_ih^T  (fp32, one-time) ----------------
__global__ __launch_bounds__(256) void prep_wc(const float* __restrict__ W,
                                               const float* __restrict__ w_ih) {
    int s = blockIdx.z;
    int j0 = blockIdx.x * 16, k0 = blockIdx.y * 16;
    __shared__ float Aw[16][200];   // W[s][k0+r][c]
    __shared__ float Bw[16][200];   // w_ih[j0+r][c]
    int tid = threadIdx.x;
    for (int i = tid; i < 16 * 200; i += 256) {
        int r = i / 200, c = i % 200;
        Aw[r][c] = (k0 + r < D)   ? W[(size_t)s * D * D + (k0 + r) * D + c] : 0.f;
        Bw[r][c] = (j0 + r < 600) ? w_ih[(size_t)(j0 + r) * D + c] : 0.f;
    }
    __syncthreads();
    int ty = tid / 16, tx = tid % 16;       // ty -> k, tx -> j
    float acc = 0.f;
#pragma unroll 8
    for (int c = 0; c < 200; c++) acc += Aw[ty][c] * Bw[tx][c];
    if (k0 + ty < D && j0 + tx < 600)
        g_Wc[(size_t)s * D * 600 + (k0 + ty) * 600 + (j0 + tx)] = acc;
}

// ---------------- prep: weight images + biases ----------------
__global__ void prep_w(const float* __restrict__ w_hh,
                       const float* __restrict__ b_hh, const float* __restrict__ b_ih) {
    const int T1 = NUM_STEPS * KEFF * (NPAD / 8);
    const int T2 = KEFF * (NPAD / 8);
    int t = blockIdx.x * blockDim.x + threadIdx.x;
    if (t < T1) {
        int c8 = t % (NPAD / 8); int x = t / (NPAD / 8);
        int k = x % KEFF; int s = x / KEFF;
        int part = k / KPART, kk = k % KPART;
        int j0 = c8 * 8;
        __nv_bfloat16 out[8];
#pragma unroll
        for (int j = 0; j < 8; j++) {
            int col = j0 + j;
            float v = (kk < D && col < 600) ? g_Wc[(size_t)s * D * 600 + kk * 600 + col] : 0.f;
            __nv_bfloat16 hi = __float2bfloat16_rn(v);
            out[j] = (part == 1) ? __float2bfloat16_rn(v - __bfloat162float(hi)) : hi;
        }
        *(uint4*)(g_Bgi + ((size_t)(s * KEFF + k)) * NPAD + j0) = *(uint4*)out;
    } else if (t < T1 + T2) {
        int u = t - T1;
        int c8 = u % (NPAD / 8); int k = u / (NPAD / 8);
        int part = k / KPART, kk = k % KPART;
        int j0 = c8 * 8;
        __nv_bfloat16 out[8];
#pragma unroll
        for (int j = 0; j < 8; j++) {
            int col = j0 + j;
            float v = (kk < D && col < 600) ? w_hh[(size_t)col * D + kk] : 0.f;
            __nv_bfloat16 hi = __float2bfloat16_rn(v);
            out[j] = (part == 1) ? __float2bfloat16_rn(v - __bfloat162float(hi)) : hi;
        }
        *(uint4*)(g_Bhh + (size_t)k * NPAD + j0) = *(uint4*)out;
    } else {
        int u = t - T1 - T2;
        if (u < NPAD) g_bias_hh[u] = (u < 600) ? b_hh[u] : 0.f;
        else if (u < 2 * NPAD) {
            int v = u - NPAD;
            g_bias_ih[v] = (v < 600) ? b_ih[v] : 0.f;
        }
    }
}

// ---------------- dtype detect + zero CSR counters ----------------
__global__ void detect_zero(const int* __restrict__ ei32) {
    int t = blockIdx.x * blockDim.x + threadIdx.x;
    if (t < N_NODES) g_cnt[t] = 0;
    if (blockIdx.x == 0) {
        __shared__ int ok;
        if (threadIdx.x == 0) ok = 1;
        __syncthreads();
        if (ei32[2 * threadIdx.x + 1] != 0) ok = 0;
        __syncthreads();
        if (threadIdx.x == 0) g_is64 = ok;
    }
}

// ---------------- init: h = pad(x), + bf16 image, + pad-row zeros ----------------
__global__ __launch_bounds__(256) void init_fused(const float* __restrict__ x) {
    __shared__ float hs[8][KPART];
    int warp = threadIdx.x >> 5, lane = threadIdx.x & 31;
    int n = blockIdx.x * 8 + warp;
    if (n >= NODES_PAD) return;
    if (n < N_NODES) {
        for (int j = lane; j < KPART; j += 32) {
            float v = (j < IN_DIM) ? x[(size_t)n * IN_DIM + j] : 0.f;
            if (j < D) g_h[(size_t)n * D + j] = v;
            hs[warp][j] = (j < D) ? v : 0.f;
        }
        __syncwarp();
        for (int c = lane; c < NCHUNK; c += 32) {
            int j0 = c * 8;
            int part = j0 / KPART, kk0 = j0 % KPART;
            __nv_bfloat16 out[8];
#pragma unroll
            for (int q = 0; q < 8; q++) {
                float v = hs[warp][kk0 + q];
                __nv_bfloat16 hi = __float2bfloat16_rn(v);
                out[q] = (part < 2) ? hi : __float2bfloat16_rn(v - __bfloat162float(hi));
            }
            *(uint4*)(g_Ah + (size_t)n * KEFF + j0) = *(uint4*)out;
        }
    } else {
        for (int c = lane; c < NCHUNK; c += 32) {
            *(uint4*)(g_Ah + (size_t)n * KEFF + c * 8) = make_uint4(0, 0, 0, 0);
            *(uint4*)(g_As + (size_t)n * KEFF + c * 8) = make_uint4(0, 0, 0, 0);
        }
    }
}

// ---------------- CSR build (range-clamped) ----------------
__global__ void csr_count(const void* __restrict__ eiv) {
    int e = blockIdx.x * blockDim.x + threadIdx.x;
    if (e >= N_EDGES) return;
    int src, dst;
    if (g_is64) {
        const long long* ei = (const long long*)eiv;
        src = (int)ei[e]; dst = (int)ei[N_EDGES + e];
    } else {
        const int* ei = (const int*)eiv;
        src = ei[e]; dst = ei[N_EDGES + e];
    }
    if ((unsigned)src >= N_NODES || (unsigned)dst >= N_NODES) return;
    atomicAdd(&g_cnt[dst], 1);
}

__global__ void csr_scan() {     // single block, 1024 threads
    __shared__ int tsum[1024];
    int tid = threadIdx.x;
    const int CHK = (N_NODES + 1023) / 1024;
    int lo = tid * CHK;
    int hi = lo + CHK; if (hi > N_NODES) hi = N_NODES;
    int s = 0;
    for (int i = lo; i < hi; i++) s += g_cnt[i];
    tsum[tid] = s;
    __syncthreads();
    for (int off = 1; off < 1024; off <<= 1) {
        int v = (tid >= off) ? tsum[tid - off] : 0;
        __syncthreads();
        tsum[tid] += v;
        __syncthreads();
    }
    int excl = (tid == 0) ? 0 : tsum[tid - 1];
    for (int i = lo; i < hi; i++) {
        int c = g_cnt[i];
        g_row[i] = excl;
        g_cur[i] = excl;
        excl += c;
    }
    if (tid == 1023) g_row[N_NODES] = tsum[1023];
}

__global__ void csr_fill(const void* __restrict__ eiv) {
    int e = blockIdx.x * blockDim.x + threadIdx.x;
    if (e >= N_EDGES) return;
    int src, dst;
    if (g_is64) {
        const long long* ei = (const long long*)eiv;
        src = (int)ei[e]; dst = (int)ei[N_EDGES + e];
    } else {
        const int* ei = (const int*)eiv;
        src = ei[e]; dst = ei[N_EDGES + e];
    }
    if ((unsigned)src >= N_NODES || (unsigned)dst >= N_NODES) return;
    int pos = atomicAdd(&g_cur[dst], 1);
    g_csr[pos] = src;
}

// ---------------- HMMA GEMM: exact R11 (measured best: tensor 48%, 2 CTA/SM) ----------------
#define APITCH 40
#define BPITCH 136

__global__ __launch_bounds__(256) void gemm_mma(
    const __nv_bfloat16* __restrict__ A,
    const __nv_bfloat16* __restrict__ B,
    const float* __restrict__ bias,
    float* __restrict__ C, int ldb)
{
    __shared__ __nv_bfloat16 As[2][128][APITCH];
    __shared__ __nv_bfloat16 Bs[2][32][BPITCH];
    const int tid = threadIdx.x, lane = tid & 31, wid = tid >> 5;
    const int warpM = (wid & 3) * 32, warpN = (wid >> 2) * 64;
    const int row0 = blockIdx.y * 128, col0 = blockIdx.x * 128;

    float acc[2][8][4];
#pragma unroll
    for (int i = 0; i < 2; i++)
#pragma unroll
        for (int j = 0; j < 8; j++)
#pragma unroll
            for (int q = 0; q < 4; q++) acc[i][j][q] = 0.f;

#define LOAD_STAGE(ch, buf) do { \
    int _k0 = (ch) * 32; \
    _Pragma("unroll") \
    for (int it = 0; it < 2; it++) { \
        int idx = tid + it * 256; \
        int r = idx >> 2, seg = idx & 3; \
        const void* s_ = A + (size_t)(row0 + r) * KEFF + _k0 + seg * 8; \
        CP_ASYNC16(saddr(&As[buf][r][seg * 8]), s_); \
    } \
    _Pragma("unroll") \
    for (int it = 0; it < 2; it++) { \
        int idx = tid + it * 256; \
        int r = idx >> 4, seg = idx & 15; \
        const void* s_ = B + (size_t)(_k0 + r) * ldb + col0 + seg * 8; \
        CP_ASYNC16(saddr(&Bs[buf][r][seg * 8]), s_); \
    } \
    CP_COMMIT(); \
} while (0)

    LOAD_STAGE(0, 0);

    for (int ch = 0; ch < NCH; ch++) {
        int buf = ch & 1;
        if (ch + 1 < NCH) {
            LOAD_STAGE(ch + 1, buf ^ 1);
            asm volatile("cp.async.wait_group 1;");
        } else {
            asm volatile("cp.async.wait_group 0;");
        }
        __syncthreads();

#pragma unroll
        for (int kk = 0; kk < 2; kk++) {
            uint32_t a[2][4], b[4][4];
#pragma unroll
            for (int mt = 0; mt < 2; mt++)
                ldsm4(a[mt], saddr(&As[buf][warpM + mt * 16 + (lane & 15)][kk * 16 + (lane >> 4) * 8]));
#pragma unroll
            for (int nt = 0; nt < 4; nt++)
                ldsm4t(b[nt], saddr(&Bs[buf][kk * 16 + (lane & 15)][warpN + nt * 16 + (lane >> 4) * 8]));
#pragma unroll
            for (int mt = 0; mt < 2; mt++)
#pragma unroll
                for (int n8 = 0; n8 < 8; n8++)
                    mma16816(acc[mt][n8], a[mt], b[n8 >> 1][(n8 & 1) * 2], b[n8 >> 1][(n8 & 1) * 2 + 1]);
        }
        __syncthreads();
    }

#pragma unroll
    for (int mt = 0; mt < 2; mt++) {
        int r = row0 + warpM + mt * 16 + (lane >> 2);
#pragma unroll
        for (int n8 = 0; n8 < 8; n8++) {
            int c = col0 + warpN + n8 * 8 + (lane & 3) * 2;
            float b0 = bias[c], b1 = bias[c + 1];
            float2 v0 = make_float2(acc[mt][n8][0] + b0, acc[mt][n8][1] + b1);
            float2 v1 = make_float2(acc[mt][n8][2] + b0, acc[mt][n8][3] + b1);
            *(float2*)(C + (size_t)r * ldb + c) = v0;
            *(float2*)(C + (size_t)(r + 8) * ldb + c) = v1;
        }
    }
#undef LOAD_STAGE
}

// ---------------- CSR segment-sum of h -> hsum bf16 image (no atomics) ----------------
__global__ __launch_bounds__(256) void aggregate_kernel() {
    __shared__ float acc_s[KPART];
    int n = blockIdx.x;
    int j = threadIdx.x;
    int beg = g_row[n], end = g_row[n + 1];
    if (j < KPART) {
        float acc = 0.f;
        if (j < D) {
            int e = beg;
            for (; e + 1 < end; e += 2) {
                int s0 = g_csr[e], s1 = g_csr[e + 1];
                acc += g_h[(size_t)s0 * D + j] + g_h[(size_t)s1 * D + j];
            }
            if (e < end) acc += g_h[(size_t)g_csr[e] * D + j];
        }
        acc_s[j] = acc;
    }
    __syncthreads();
    if (j < NCHUNK) {
        int j0 = j * 8;
        int part = j0 / KPART, kk0 = j0 % KPART;
        __nv_bfloat16 out[8];
#pragma unroll
        for (int q = 0; q < 8; q++) {
            float v = acc_s[kk0 + q];
            __nv_bfloat16 hi = __float2bfloat16_rn(v);
            out[q] = (part < 2) ? hi : __float2bfloat16_rn(v - __bfloat162float(hi));
        }
        *(uint4*)(g_As + (size_t)n * KEFF + j0) = *(uint4*)out;
    }
}

// ---------------- fused GRU: h update + next-step bf16 image ----------------
__global__ __launch_bounds__(256) void gru_kernel() {
    __shared__ float hs[8][KPART];
    int warp = threadIdx.x >> 5, lane = threadIdx.x & 31;
    int n = blockIdx.x * 8 + warp;
    if (n >= N_NODES) return;
    size_t gb = (size_t)n * NPAD;
    size_t tb = (size_t)n * NPAD;
    for (int j = lane; j < KPART; j += 32) {
        float hnew = 0.f;
        if (j < D) {
            float ir  = g_gi[gb + j];
            float iz  = g_gi[gb + D + j];
            float in_ = g_gi[gb + 2 * D + j];
            float hr  = g_T[tb + j];
            float hz  = g_T[tb + D + j];
            float hn  = g_T[tb + 2 * D + j];
            float r = 1.f / (1.f + expf(-(ir + hr)));
            float z = 1.f / (1.f + expf(-(iz + hz)));
            float nn = tanhf(in_ + r * hn);
            float hold = g_h[(size_t)n * D + j];
            hnew = (1.f - z) * nn + z * hold;
            g_h[(size_t)n * D + j] = hnew;
        }
        hs[warp][j] = hnew;
    }
    __syncwarp();
    for (int c = lane; c < NCHUNK; c += 32) {
        int j0 = c * 8;
        int part = j0 / KPART, kk0 = j0 % KPART;
        __nv_bfloat16 out[8];
#pragma unroll
        for (int q = 0; q < 8; q++) {
            float v = hs[warp][kk0 + q];
            __nv_bfloat16 hi = __float2bfloat16_rn(v);
            out[q] = (part < 2) ? hi : __float2bfloat16_rn(v - __bfloat162float(hi));
        }
        *(uint4*)(g_Ah + (size_t)n * KEFF + j0) = *(uint4*)out;
    }
}

// ---------------- global max pool + classifier ----------------
__global__ void pool_kernel() {
    int j = blockIdx.x;
    float m = -3.402823466e38f;
    for (int n = threadIdx.x; n < N_NODES; n += 256)
        m = fmaxf(m, g_h[(size_t)n * D + j]);
    __shared__ float s[256];
    s[threadIdx.x] = m;
    __syncthreads();
    for (int o = 128; o > 0; o >>= 1) {
        if (threadIdx.x < o) s[threadIdx.x] = fmaxf(s[threadIdx.x], s[threadIdx.x + o]);
        __syncthreads();
    }
    if (threadIdx.x == 0) g_pool[j] = fmaxf(s[0], 0.f);
}

__global__ void cls_kernel(const float* __restrict__ cls_w,
                           const float* __restrict__ cls_b,
                           float* __restrict__ out) {
    if (blockIdx.x == 0 && threadIdx.x == 0) {
        float l0 = cls_b[0], l1 = cls_b[1];
        for (int j = 0; j < D; j++) {
            float p = g_pool[j];
            l0 += p * cls_w[j];
            l1 += p * cls_w[D + j];
        }
        float mx = fmaxf(l0, l1);
        float e0 = expf(l0 - mx), e1 = expf(l1 - mx);
        float s = e0 + e1;
        out[0] = e0 / s;
        out[1] = e1 / s;
    }
}

// ---------------- host launcher ----------------
extern "C" void kernel_launch(void* const* d_in, const int* in_sizes, int n_in,
                              void* d_out, int out_size) {
    const float* x     = (const float*)d_in[0];
    const float* W     = (const float*)d_in[1];
    const float* w_ih  = (const float*)d_in[2];
    const float* w_hh  = (const float*)d_in[3];
    const float* b_ih  = (const float*)d_in[4];
    const float* b_hh  = (const float*)d_in[5];
    const float* cls_w = (const float*)d_in[6];
    const float* cls_b = (const float*)d_in[7];
    const void*  ei    = (const void*)d_in[8];
    float* out = (float*)d_out;

    float *T_p, *gi_p, *bhh_p, *bih_p;
    __nv_bfloat16 *Ah_p, *As_p, *Bgi_p, *Bhh_p;
    cudaGetSymbolAddress((void**)&T_p,   g_T);
    cudaGetSymbolAddress((void**)&gi_p,  g_gi);
    cudaGetSymbolAddress((void**)&Ah_p,  g_Ah);
    cudaGetSymbolAddress((void**)&As_p,  g_As);
    cudaGetSymbolAddress((void**)&Bgi_p, g_Bgi);
    cudaGetSymbolAddress((void**)&Bhh_p, g_Bhh);
    cudaGetSymbolAddress((void**)&bhh_p, g_bias_hh);
    cudaGetSymbolAddress((void**)&bih_p, g_bias_ih);

    const int TB = 256;
    const int PREP_TOTAL = NUM_STEPS * KEFF * (NPAD / 8) + KEFF * (NPAD / 8) + 2 * NPAD;

    prep_wc<<<dim3(38, 13, NUM_STEPS), 256>>>(W, w_ih);                                 // 0
    prep_w<<<(PREP_TOTAL + TB - 1) / TB, TB>>>(w_hh, b_hh, b_ih);                       // 1
    detect_zero<<<(N_NODES + TB - 1) / TB, TB>>>((const int*)ei);                       // 2
    init_fused<<<(NODES_PAD + 7) / 8, 256>>>(x);                                        // 3
    csr_count<<<(N_EDGES + TB - 1) / TB, TB>>>(ei);                                     // 4
    csr_scan<<<1, 1024>>>();                                                            // 5
    csr_fill<<<(N_EDGES + TB - 1) / TB, TB>>>(ei);                                      // 6

    dim3 grid(NT, M_TILES);
    for (int s = 0; s < NUM_STEPS; s++) {
        aggregate_kernel<<<N_NODES, 256>>>();                                            // hsum of h_s
        gemm_mma<<<grid, 256>>>(Ah_p, Bhh_p, bhh_p, T_p, NPAD);                          // gh
        gemm_mma<<<grid, 256>>>(As_p, Bgi_p + (size_t)s * KEFF * NPAD, bih_p, gi_p, NPAD); // gi
        gru_kernel<<<(N_NODES + 7) / 8, 256>>>();
    }

    pool_kernel<<<D, 256>>>();
    cls_kernel<<<1, 32>>>(cls_w, cls_b, out);
}

// round 16
// speedup vs baseline: 3.1003x; 1.6226x over previous
#include <cuda_runtime.h>
#include <cuda_fp16.h>
#include <math.h>
#include <stdint.h>

#define N_NODES   100000
#define N_EDGES   400000
#define IN_DIM    100
#define D         200
#define NUM_STEPS 4

#define M_TILES    782            // ceil(100000/128)
#define NODES_PAD  (M_TILES*128)  // 100096
#define KEFF       224            // single fp16 term (200 real + pad)
#define NCH        7              // KEFF / 32
#define NCHUNK     28             // KEFF / 8
#define NT         5              // N tiles (600 -> 640)
#define NPAD       640

// ---------------- device scratch ----------------
__device__ float g_h[N_NODES * D];
__device__ float g_T[(size_t)NODES_PAD * NPAD];             // gh
__device__ float g_gi[(size_t)NODES_PAD * NPAD];            // gi
__device__ float g_Wc[NUM_STEPS * D * 600];                 // W[i] @ w_ih^T (fp32)
__device__ __align__(16) __half g_Ah[(size_t)NODES_PAD * KEFF];   // h image
__device__ __align__(16) __half g_As[(size_t)NODES_PAD * KEFF];   // hsum image
__device__ __align__(16) __half g_Bgi[(size_t)NUM_STEPS * KEFF * NPAD];  // Wc images
__device__ __align__(16) __half g_Bhh[(size_t)KEFF * NPAD];              // w_hh^T image
__device__ float g_bias_hh[NPAD];
__device__ float g_bias_ih[NPAD];
__device__ float g_pool[D];
__device__ int   g_is64;
__device__ int   g_cnt[N_NODES];
__device__ int   g_row[N_NODES + 1];
__device__ int   g_cur[N_NODES];
__device__ int   g_csr[N_EDGES];

// ---------------- PTX helpers ----------------
__device__ __forceinline__ uint32_t saddr(const void* p) {
    uint32_t a;
    asm("{ .reg .u64 t; cvta.to.shared.u64 t, %1; cvt.u32.u64 %0, t; }" : "=r"(a) : "l"(p));
    return a;
}
#define CP_ASYNC16(dst, src) \
    asm volatile("cp.async.cg.shared.global [%0], [%1], 16;" :: "r"(dst), "l"(src))
#define CP_COMMIT() asm volatile("cp.async.commit_group;")

__device__ __forceinline__ void ldsm4(uint32_t* r, uint32_t a) {
    asm volatile("ldmatrix.sync.aligned.m8n8.x4.shared.b16 {%0,%1,%2,%3}, [%4];"
        : "=r"(r[0]), "=r"(r[1]), "=r"(r[2]), "=r"(r[3]) : "r"(a));
}
__device__ __forceinline__ void ldsm4t(uint32_t* r, uint32_t a) {
    asm volatile("ldmatrix.sync.aligned.m8n8.x4.trans.shared.b16 {%0,%1,%2,%3}, [%4];"
        : "=r"(r[0]), "=r"(r[1]), "=r"(r[2]), "=r"(r[3]) : "r"(a));
}
__device__ __forceinline__ void mma16816(float* c, const uint32_t* a, uint32_t b0, uint32_t b1) {
    asm volatile("mma.sync.aligned.m16n8k16.row.col.f32.f16.f16.f32 "
        "{%0,%1,%2,%3}, {%4,%5,%6,%7}, {%8,%9}, {%0,%1,%2,%3};"
        : "+f"(c[0]), "+f"(c[1]), "+f"(c[2]), "+f"(c[3])
        : "r"(a[0]), "r"(a[1]), "r"(a[2]), "r"(a[3]), "r"(b0), "r"(b1));
}

// ---------------- prep_wc: Wc[s] = W[s] @ w_ih^T  (fp32, one-time) ----------------
__global__ __launch_bounds__(256) void prep_wc(const float* __restrict__ W,
                                               const float* __restrict__ w_ih) {
    int s = blockIdx.z;
    int j0 = blockIdx.x * 16, k0 = blockIdx.y * 16;
    __shared__ float Aw[16][200];
    __shared__ float Bw[16][200];
    int tid = threadIdx.x;
    for (int i = tid; i < 16 * 200; i += 256) {
        int r = i / 200, c = i % 200;
        Aw[r][c] = (k0 + r < D)   ? W[(size_t)s * D * D + (k0 + r) * D + c] : 0.f;
        Bw[r][c] = (j0 + r < 600) ? w_ih[(size_t)(j0 + r) * D + c] : 0.f;
    }
    __syncthreads();
    int ty = tid / 16, tx = tid % 16;
    float acc = 0.f;
#pragma unroll 8
    for (int c = 0; c < 200; c++) acc += Aw[ty][c] * Bw[tx][c];
    if (k0 + ty < D && j0 + tx < 600)
        g_Wc[(size_t)s * D * 600 + (k0 + ty) * 600 + (j0 + tx)] = acc;
}

// ---------------- prep: weight images + biases ----------------
__global__ void prep_w(const float* __restrict__ w_hh,
                       const float* __restrict__ b_hh, const float* __restrict__ b_ih) {
    const int T1 = NUM_STEPS * KEFF * (NPAD / 8);
    const int T2 = KEFF * (NPAD / 8);
    int t = blockIdx.x * blockDim.x + threadIdx.x;
    if (t < T1) {
        int c8 = t % (NPAD / 8); int x = t / (NPAD / 8);
        int k = x % KEFF; int s = x / KEFF;
        int j0 = c8 * 8;
        __half out[8];
#pragma unroll
        for (int j = 0; j < 8; j++) {
            int col = j0 + j;
            float v = (k < D && col < 600) ? g_Wc[(size_t)s * D * 600 + k * 600 + col] : 0.f;
            out[j] = __float2half_rn(v);
        }
        *(uint4*)(g_Bgi + ((size_t)(s * KEFF + k)) * NPAD + j0) = *(uint4*)out;
    } else if (t < T1 + T2) {
        int u = t - T1;
        int c8 = u % (NPAD / 8); int k = u / (NPAD / 8);
        int j0 = c8 * 8;
        __half out[8];
#pragma unroll
        for (int j = 0; j < 8; j++) {
            int col = j0 + j;
            float v = (k < D && col < 600) ? w_hh[(size_t)col * D + k] : 0.f;
            out[j] = __float2half_rn(v);
        }
        *(uint4*)(g_Bhh + (size_t)k * NPAD + j0) = *(uint4*)out;
    } else {
        int u = t - T1 - T2;
        if (u < NPAD) g_bias_hh[u] = (u < 600) ? b_hh[u] : 0.f;
        else if (u < 2 * NPAD) {
            int v = u - NPAD;
            g_bias_ih[v] = (v < 600) ? b_ih[v] : 0.f;
        }
    }
}

// ---------------- dtype detect + zero CSR counters ----------------
__global__ void detect_zero(const int* __restrict__ ei32) {
    int t = blockIdx.x * blockDim.x + threadIdx.x;
    if (t < N_NODES) g_cnt[t] = 0;
    if (blockIdx.x == 0) {
        __shared__ int ok;
        if (threadIdx.x == 0) ok = 1;
        __syncthreads();
        if (ei32[2 * threadIdx.x + 1] != 0) ok = 0;
        __syncthreads();
        if (threadIdx.x == 0) g_is64 = ok;
    }
}

// ---------------- init: h = pad(x), + fp16 image, + pad-row zeros ----------------
__global__ __launch_bounds__(256) void init_fused(const float* __restrict__ x) {
    __shared__ float hs[8][KEFF];
    int warp = threadIdx.x >> 5, lane = threadIdx.x & 31;
    int n = blockIdx.x * 8 + warp;
    if (n >= NODES_PAD) return;
    if (n < N_NODES) {
        for (int j = lane; j < KEFF; j += 32) {
            float v = (j < IN_DIM) ? x[(size_t)n * IN_DIM + j] : 0.f;
            if (j < D) g_h[(size_t)n * D + j] = v;
            hs[warp][j] = (j < D) ? v : 0.f;
        }
        __syncwarp();
        for (int c = lane; c < NCHUNK; c += 32) {
            int j0 = c * 8;
            __half out[8];
#pragma unroll
            for (int q = 0; q < 8; q++) out[q] = __float2half_rn(hs[warp][j0 + q]);
            *(uint4*)(g_Ah + (size_t)n * KEFF + j0) = *(uint4*)out;
        }
    } else {
        for (int c = lane; c < NCHUNK; c += 32) {
            *(uint4*)(g_Ah + (size_t)n * KEFF + c * 8) = make_uint4(0, 0, 0, 0);
            *(uint4*)(g_As + (size_t)n * KEFF + c * 8) = make_uint4(0, 0, 0, 0);
        }
    }
}

// ---------------- CSR build (range-clamped) ----------------
__global__ void csr_count(const void* __restrict__ eiv) {
    int e = blockIdx.x * blockDim.x + threadIdx.x;
    if (e >= N_EDGES) return;
    int src, dst;
    if (g_is64) {
        const long long* ei = (const long long*)eiv;
        src = (int)ei[e]; dst = (int)ei[N_EDGES + e];
    } else {
        const int* ei = (const int*)eiv;
        src = ei[e]; dst = ei[N_EDGES + e];
    }
    if ((unsigned)src >= N_NODES || (unsigned)dst >= N_NODES) return;
    atomicAdd(&g_cnt[dst], 1);
}

__global__ void csr_scan() {     // single block, 1024 threads
    __shared__ int tsum[1024];
    int tid = threadIdx.x;
    const int CHK = (N_NODES + 1023) / 1024;
    int lo = tid * CHK;
    int hi = lo + CHK; if (hi > N_NODES) hi = N_NODES;
    int s = 0;
    for (int i = lo; i < hi; i++) s += g_cnt[i];
    tsum[tid] = s;
    __syncthreads();
    for (int off = 1; off < 1024; off <<= 1) {
        int v = (tid >= off) ? tsum[tid - off] : 0;
        __syncthreads();
        tsum[tid] += v;
        __syncthreads();
    }
    int excl = (tid == 0) ? 0 : tsum[tid - 1];
    for (int i = lo; i < hi; i++) {
        int c = g_cnt[i];
        g_row[i] = excl;
        g_cur[i] = excl;
        excl += c;
    }
    if (tid == 1023) g_row[N_NODES] = tsum[1023];
}

__global__ void csr_fill(const void* __restrict__ eiv) {
    int e = blockIdx.x * blockDim.x + threadIdx.x;
    if (e >= N_EDGES) return;
    int src, dst;
    if (g_is64) {
        const long long* ei = (const long long*)eiv;
        src = (int)ei[e]; dst = (int)ei[N_EDGES + e];
    } else {
        const int* ei = (const int*)eiv;
        src = ei[e]; dst = ei[N_EDGES + e];
    }
    if ((unsigned)src >= N_NODES || (unsigned)dst >= N_NODES) return;
    int pos = atomicAdd(&g_cur[dst], 1);
    g_csr[pos] = src;
}

// ---------------- HMMA GEMM: R11 structure, fp16 operands, K=224 ----------------
#define APITCH 40
#define BPITCH 136

__global__ __launch_bounds__(256) void gemm_mma(
    const __half* __restrict__ A,
    const __half* __restrict__ B,
    const float* __restrict__ bias,
    float* __restrict__ C, int ldb)
{
    __shared__ __half As[2][128][APITCH];
    __shared__ __half Bs[2][32][BPITCH];
    const int tid = threadIdx.x, lane = tid & 31, wid = tid >> 5;
    const int warpM = (wid & 3) * 32, warpN = (wid >> 2) * 64;
    const int row0 = blockIdx.y * 128, col0 = blockIdx.x * 128;

    float acc[2][8][4];
#pragma unroll
    for (int i = 0; i < 2; i++)
#pragma unroll
        for (int j = 0; j < 8; j++)
#pragma unroll
            for (int q = 0; q < 4; q++) acc[i][j][q] = 0.f;

#define LOAD_STAGE(ch, buf) do { \
    int _k0 = (ch) * 32; \
    _Pragma("unroll") \
    for (int it = 0; it < 2; it++) { \
        int idx = tid + it * 256; \
        int r = idx >> 2, seg = idx & 3; \
        const void* s_ = A + (size_t)(row0 + r) * KEFF + _k0 + seg * 8; \
        CP_ASYNC16(saddr(&As[buf][r][seg * 8]), s_); \
    } \
    _Pragma("unroll") \
    for (int it = 0; it < 2; it++) { \
        int idx = tid + it * 256; \
        int r = idx >> 4, seg = idx & 15; \
        const void* s_ = B + (size_t)(_k0 + r) * ldb + col0 + seg * 8; \
        CP_ASYNC16(saddr(&Bs[buf][r][seg * 8]), s_); \
    } \
    CP_COMMIT(); \
} while (0)

    LOAD_STAGE(0, 0);

    for (int ch = 0; ch < NCH; ch++) {
        int buf = ch & 1;
        if (ch + 1 < NCH) {
            LOAD_STAGE(ch + 1, buf ^ 1);
            asm volatile("cp.async.wait_group 1;");
        } else {
            asm volatile("cp.async.wait_group 0;");
        }
        __syncthreads();

#pragma unroll
        for (int kk = 0; kk < 2; kk++) {
            uint32_t a[2][4], b[4][4];
#pragma unroll
            for (int mt = 0; mt < 2; mt++)
                ldsm4(a[mt], saddr(&As[buf][warpM + mt * 16 + (lane & 15)][kk * 16 + (lane >> 4) * 8]));
#pragma unroll
            for (int nt = 0; nt < 4; nt++)
                ldsm4t(b[nt], saddr(&Bs[buf][kk * 16 + (lane & 15)][warpN + nt * 16 + (lane >> 4) * 8]));
#pragma unroll
            for (int mt = 0; mt < 2; mt++)
#pragma unroll
                for (int n8 = 0; n8 < 8; n8++)
                    mma16816(acc[mt][n8], a[mt], b[n8 >> 1][(n8 & 1) * 2], b[n8 >> 1][(n8 & 1) * 2 + 1]);
        }
        __syncthreads();
    }

#pragma unroll
    for (int mt = 0; mt < 2; mt++) {
        int r = row0 + warpM + mt * 16 + (lane >> 2);
#pragma unroll
        for (int n8 = 0; n8 < 8; n8++) {
            int c = col0 + warpN + n8 * 8 + (lane & 3) * 2;
            float b0 = bias[c], b1 = bias[c + 1];
            float2 v0 = make_float2(acc[mt][n8][0] + b0, acc[mt][n8][1] + b1);
            float2 v1 = make_float2(acc[mt][n8][2] + b0, acc[mt][n8][3] + b1);
            *(float2*)(C + (size_t)r * ldb + c) = v0;
            *(float2*)(C + (size_t)(r + 8) * ldb + c) = v1;
        }
    }
#undef LOAD_STAGE
}

// ---------------- CSR segment-sum of h -> hsum fp16 image (no atomics) ----------------
__global__ __launch_bounds__(256) void aggregate_kernel() {
    __shared__ float acc_s[KEFF];
    int n = blockIdx.x;
    int j = threadIdx.x;
    int beg = g_row[n], end = g_row[n + 1];
    if (j < KEFF) {
        float acc = 0.f;
        if (j < D) {
            int e = beg;
            for (; e + 1 < end; e += 2) {
                int s0 = g_csr[e], s1 = g_csr[e + 1];
                acc += g_h[(size_t)s0 * D + j] + g_h[(size_t)s1 * D + j];
            }
            if (e < end) acc += g_h[(size_t)g_csr[e] * D + j];
        }
        acc_s[j] = acc;
    }
    __syncthreads();
    if (j < NCHUNK) {
        int j0 = j * 8;
        __half out[8];
#pragma unroll
        for (int q = 0; q < 8; q++) out[q] = __float2half_rn(acc_s[j0 + q]);
        *(uint4*)(g_As + (size_t)n * KEFF + j0) = *(uint4*)out;
    }
}

// ---------------- fused GRU: h update + next-step fp16 image ----------------
__global__ __launch_bounds__(256) void gru_kernel() {
    __shared__ float hs[8][KEFF];
    int warp = threadIdx.x >> 5, lane = threadIdx.x & 31;
    int n = blockIdx.x * 8 + warp;
    if (n >= N_NODES) return;
    size_t gb = (size_t)n * NPAD;
    size_t tb = (size_t)n * NPAD;
    for (int j = lane; j < KEFF; j += 32) {
        float hnew = 0.f;
        if (j < D) {
            float ir  = g_gi[gb + j];
            float iz  = g_gi[gb + D + j];
            float in_ = g_gi[gb + 2 * D + j];
            float hr  = g_T[tb + j];
            float hz  = g_T[tb + D + j];
            float hn  = g_T[tb + 2 * D + j];
            float r = 1.f / (1.f + expf(-(ir + hr)));
            float z = 1.f / (1.f + expf(-(iz + hz)));
            float nn = tanhf(in_ + r * hn);
            float hold = g_h[(size_t)n * D + j];
            hnew = (1.f - z) * nn + z * hold;
            g_h[(size_t)n * D + j] = hnew;
        }
        hs[warp][j] = hnew;
    }
    __syncwarp();
    for (int c = lane; c < NCHUNK; c += 32) {
        int j0 = c * 8;
        __half out[8];
#pragma unroll
        for (int q = 0; q < 8; q++) out[q] = __float2half_rn(hs[warp][j0 + q]);
        *(uint4*)(g_Ah + (size_t)n * KEFF + j0) = *(uint4*)out;
    }
}

// ---------------- global max pool + classifier ----------------
__global__ void pool_kernel() {
    int j = blockIdx.x;
    float m = -3.402823466e38f;
    for (int n = threadIdx.x; n < N_NODES; n += 256)
        m = fmaxf(m, g_h[(size_t)n * D + j]);
    __shared__ float s[256];
    s[threadIdx.x] = m;
    __syncthreads();
    for (int o = 128; o > 0; o >>= 1) {
        if (threadIdx.x < o) s[threadIdx.x] = fmaxf(s[threadIdx.x], s[threadIdx.x + o]);
        __syncthreads();
    }
    if (threadIdx.x == 0) g_pool[j] = fmaxf(s[0], 0.f);
}

__global__ void cls_kernel(const float* __restrict__ cls_w,
                           const float* __restrict__ cls_b,
                           float* __restrict__ out) {
    if (blockIdx.x == 0 && threadIdx.x == 0) {
        float l0 = cls_b[0], l1 = cls_b[1];
        for (int j = 0; j < D; j++) {
            float p = g_pool[j];
            l0 += p * cls_w[j];
            l1 += p * cls_w[D + j];
        }
        float mx = fmaxf(l0, l1);
        float e0 = expf(l0 - mx), e1 = expf(l1 - mx);
        float s = e0 + e1;
        out[0] = e0 / s;
        out[1] = e1 / s;
    }
}

// ---------------- host launcher ----------------
extern "C" void kernel_launch(void* const* d_in, const int* in_sizes, int n_in,
                              void* d_out, int out_size) {
    const float* x     = (const float*)d_in[0];
    const float* W     = (const float*)d_in[1];
    const float* w_ih  = (const float*)d_in[2];
    const float* w_hh  = (const float*)d_in[3];
    const float* b_ih  = (const float*)d_in[4];
    const float* b_hh  = (const float*)d_in[5];
    const float* cls_w = (const float*)d_in[6];
    const float* cls_b = (const float*)d_in[7];
    const void*  ei    = (const void*)d_in[8];
    float* out = (float*)d_out;

    float *T_p, *gi_p, *bhh_p, *bih_p;
    __half *Ah_p, *As_p, *Bgi_p, *Bhh_p;
    cudaGetSymbolAddress((void**)&T_p,   g_T);
    cudaGetSymbolAddress((void**)&gi_p,  g_gi);
    cudaGetSymbolAddress((void**)&Ah_p,  g_Ah);
    cudaGetSymbolAddress((void**)&As_p,  g_As);
    cudaGetSymbolAddress((void**)&Bgi_p, g_Bgi);
    cudaGetSymbolAddress((void**)&Bhh_p, g_Bhh);
    cudaGetSymbolAddress((void**)&bhh_p, g_bias_hh);
    cudaGetSymbolAddress((void**)&bih_p, g_bias_ih);

    const int TB = 256;
    const int PREP_TOTAL = NUM_STEPS * KEFF * (NPAD / 8) + KEFF * (NPAD / 8) + 2 * NPAD;

    prep_wc<<<dim3(38, 13, NUM_STEPS), 256>>>(W, w_ih);
    prep_w<<<(PREP_TOTAL + TB - 1) / TB, TB>>>(w_hh, b_hh, b_ih);
    detect_zero<<<(N_NODES + TB - 1) / TB, TB>>>((const int*)ei);
    init_fused<<<(NODES_PAD + 7) / 8, 256>>>(x);
    csr_count<<<(N_EDGES + TB - 1) / TB, TB>>>(ei);
    csr_scan<<<1, 1024>>>();
    csr_fill<<<(N_EDGES + TB - 1) / TB, TB>>>(ei);

    dim3 grid(NT, M_TILES);
    for (int s = 0; s < NUM_STEPS; s++) {
        aggregate_kernel<<<N_NODES, 256>>>();
        gemm_mma<<<grid, 256>>>(Ah_p, Bhh_p, bhh_p, T_p, NPAD);
        gemm_mma<<<grid, 256>>>(As_p, Bgi_p + (size_t)s * KEFF * NPAD, bih_p, gi_p, NPAD);
        gru_kernel<<<(N_NODES + 7) / 8, 256>>>();
    }

    pool_kernel<<<D, 256>>>();
    cls_kernel<<<1, 32>>>(cls_w, cls_b, out);
}

// round 17
// speedup vs baseline: 3.9600x; 1.2773x over previous
#include <cuda_runtime.h>
#include <cuda_fp16.h>
#include <math.h>
#include <stdint.h>

#define N_NODES   100000
#define N_EDGES   400000
#define IN_DIM    100
#define D         200
#define NUM_STEPS 4

#define M_TILES    782            // ceil(100000/128)
#define NODES_PAD  (M_TILES*128)  // 100096
#define KEFF       224            // single fp16 term (200 real + pad)
#define NCH        7              // KEFF / 32
#define NCHUNK     28             // KEFF / 8
#define NT         5              // N tiles (600 -> 640)
#define NPAD       640

// ---------------- device scratch ----------------
__device__ float g_h[N_NODES * D];
__device__ __align__(16) __half g_T[(size_t)NODES_PAD * NPAD];    // gh (fp16)
__device__ __align__(16) __half g_gi[(size_t)NODES_PAD * NPAD];   // gi (fp16)
__device__ float g_Wc[NUM_STEPS * D * 600];                 // W[i] @ w_ih^T (fp32)
__device__ __align__(16) __half g_Ah[(size_t)NODES_PAD * KEFF];   // h image
__device__ __align__(16) __half g_As[(size_t)NODES_PAD * KEFF];   // hsum image
__device__ __align__(16) __half g_Bgi[(size_t)NUM_STEPS * KEFF * NPAD];  // Wc images
__device__ __align__(16) __half g_Bhh[(size_t)KEFF * NPAD];              // w_hh^T image
__device__ float g_bias_hh[NPAD];
__device__ float g_bias_ih[NPAD];
__device__ float g_pool[D];
__device__ int   g_is64;
__device__ int   g_cnt[N_NODES];
__device__ int   g_row[N_NODES + 1];
__device__ int   g_cur[N_NODES];
__device__ int   g_csr[N_EDGES];

// ---------------- PTX helpers ----------------
__device__ __forceinline__ uint32_t saddr(const void* p) {
    uint32_t a;
    asm("{ .reg .u64 t; cvta.to.shared.u64 t, %1; cvt.u32.u64 %0, t; }" : "=r"(a) : "l"(p));
    return a;
}
#define CP_ASYNC16(dst, src) \
    asm volatile("cp.async.cg.shared.global [%0], [%1], 16;" :: "r"(dst), "l"(src))
#define CP_COMMIT() asm volatile("cp.async.commit_group;")

__device__ __forceinline__ void ldsm4(uint32_t* r, uint32_t a) {
    asm volatile("ldmatrix.sync.aligned.m8n8.x4.shared.b16 {%0,%1,%2,%3}, [%4];"
        : "=r"(r[0]), "=r"(r[1]), "=r"(r[2]), "=r"(r[3]) : "r"(a));
}
__device__ __forceinline__ void ldsm4t(uint32_t* r, uint32_t a) {
    asm volatile("ldmatrix.sync.aligned.m8n8.x4.trans.shared.b16 {%0,%1,%2,%3}, [%4];"
        : "=r"(r[0]), "=r"(r[1]), "=r"(r[2]), "=r"(r[3]) : "r"(a));
}
__device__ __forceinline__ void mma16816(float* c, const uint32_t* a, uint32_t b0, uint32_t b1) {
    asm volatile("mma.sync.aligned.m16n8k16.row.col.f32.f16.f16.f32 "
        "{%0,%1,%2,%3}, {%4,%5,%6,%7}, {%8,%9}, {%0,%1,%2,%3};"
        : "+f"(c[0]), "+f"(c[1]), "+f"(c[2]), "+f"(c[3])
        : "r"(a[0]), "r"(a[1]), "r"(a[2]), "r"(a[3]), "r"(b0), "r"(b1));
}

// ---------------- prep_wc: Wc[s] = W[s] @ w_ih^T  (fp32, one-time) ----------------
__global__ __launch_bounds__(256) void prep_wc(const float* __restrict__ W,
                                               const float* __restrict__ w_ih) {
    int s = blockIdx.z;
    int j0 = blockIdx.x * 16, k0 = blockIdx.y * 16;
    __shared__ float Aw[16][200];
    __shared__ float Bw[16][200];
    int tid = threadIdx.x;
    for (int i = tid; i < 16 * 200; i += 256) {
        int r = i / 200, c = i % 200;
        Aw[r][c] = (k0 + r < D)   ? W[(size_t)s * D * D + (k0 + r) * D + c] : 0.f;
        Bw[r][c] = (j0 + r < 600) ? w_ih[(size_t)(j0 + r) * D + c] : 0.f;
    }
    __syncthreads();
    int ty = tid / 16, tx = tid % 16;
    float acc = 0.f;
#pragma unroll 8
    for (int c = 0; c < 200; c++) acc += Aw[ty][c] * Bw[tx][c];
    if (k0 + ty < D && j0 + tx < 600)
        g_Wc[(size_t)s * D * 600 + (k0 + ty) * 600 + (j0 + tx)] = acc;
}

// ---------------- prep: weight images + biases ----------------
__global__ void prep_w(const float* __restrict__ w_hh,
                       const float* __restrict__ b_hh, const float* __restrict__ b_ih) {
    const int T1 = NUM_STEPS * KEFF * (NPAD / 8);
    const int T2 = KEFF * (NPAD / 8);
    int t = blockIdx.x * blockDim.x + threadIdx.x;
    if (t < T1) {
        int c8 = t % (NPAD / 8); int x = t / (NPAD / 8);
        int k = x % KEFF; int s = x / KEFF;
        int j0 = c8 * 8;
        __half out[8];
#pragma unroll
        for (int j = 0; j < 8; j++) {
            int col = j0 + j;
            float v = (k < D && col < 600) ? g_Wc[(size_t)s * D * 600 + k * 600 + col] : 0.f;
            out[j] = __float2half_rn(v);
        }
        *(uint4*)(g_Bgi + ((size_t)(s * KEFF + k)) * NPAD + j0) = *(uint4*)out;
    } else if (t < T1 + T2) {
        int u = t - T1;
        int c8 = u % (NPAD / 8); int k = u / (NPAD / 8);
        int j0 = c8 * 8;
        __half out[8];
#pragma unroll
        for (int j = 0; j < 8; j++) {
            int col = j0 + j;
            float v = (k < D && col < 600) ? w_hh[(size_t)col * D + k] : 0.f;
            out[j] = __float2half_rn(v);
        }
        *(uint4*)(g_Bhh + (size_t)k * NPAD + j0) = *(uint4*)out;
    } else {
        int u = t - T1 - T2;
        if (u < NPAD) g_bias_hh[u] = (u < 600) ? b_hh[u] : 0.f;
        else if (u < 2 * NPAD) {
            int v = u - NPAD;
            g_bias_ih[v] = (v < 600) ? b_ih[v] : 0.f;
        }
    }
}

// ---------------- dtype detect + zero CSR counters ----------------
__global__ void detect_zero(const int* __restrict__ ei32) {
    int t = blockIdx.x * blockDim.x + threadIdx.x;
    if (t < N_NODES) g_cnt[t] = 0;
    if (blockIdx.x == 0) {
        __shared__ int ok;
        if (threadIdx.x == 0) ok = 1;
        __syncthreads();
        if (ei32[2 * threadIdx.x + 1] != 0) ok = 0;
        __syncthreads();
        if (threadIdx.x == 0) g_is64 = ok;
    }
}

// ---------------- init: h = pad(x), + fp16 image, + pad-row zeros ----------------
__global__ __launch_bounds__(256) void init_fused(const float* __restrict__ x) {
    __shared__ float hs[8][KEFF];
    int warp = threadIdx.x >> 5, lane = threadIdx.x & 31;
    int n = blockIdx.x * 8 + warp;
    if (n >= NODES_PAD) return;
    if (n < N_NODES) {
        for (int j = lane; j < KEFF; j += 32) {
            float v = (j < IN_DIM) ? x[(size_t)n * IN_DIM + j] : 0.f;
            if (j < D) g_h[(size_t)n * D + j] = v;
            hs[warp][j] = (j < D) ? v : 0.f;
        }
        __syncwarp();
        for (int c = lane; c < NCHUNK; c += 32) {
            int j0 = c * 8;
            __half out[8];
#pragma unroll
            for (int q = 0; q < 8; q++) out[q] = __float2half_rn(hs[warp][j0 + q]);
            *(uint4*)(g_Ah + (size_t)n * KEFF + j0) = *(uint4*)out;
        }
    } else {
        for (int c = lane; c < NCHUNK; c += 32) {
            *(uint4*)(g_Ah + (size_t)n * KEFF + c * 8) = make_uint4(0, 0, 0, 0);
            *(uint4*)(g_As + (size_t)n * KEFF + c * 8) = make_uint4(0, 0, 0, 0);
        }
    }
}

// ---------------- CSR build (range-clamped) ----------------
__global__ void csr_count(const void* __restrict__ eiv) {
    int e = blockIdx.x * blockDim.x + threadIdx.x;
    if (e >= N_EDGES) return;
    int src, dst;
    if (g_is64) {
        const long long* ei = (const long long*)eiv;
        src = (int)ei[e]; dst = (int)ei[N_EDGES + e];
    } else {
        const int* ei = (const int*)eiv;
        src = ei[e]; dst = ei[N_EDGES + e];
    }
    if ((unsigned)src >= N_NODES || (unsigned)dst >= N_NODES) return;
    atomicAdd(&g_cnt[dst], 1);
}

__global__ void csr_scan() {     // single block, 1024 threads
    __shared__ int tsum[1024];
    int tid = threadIdx.x;
    const int CHK = (N_NODES + 1023) / 1024;
    int lo = tid * CHK;
    int hi = lo + CHK; if (hi > N_NODES) hi = N_NODES;
    int s = 0;
    for (int i = lo; i < hi; i++) s += g_cnt[i];
    tsum[tid] = s;
    __syncthreads();
    for (int off = 1; off < 1024; off <<= 1) {
        int v = (tid >= off) ? tsum[tid - off] : 0;
        __syncthreads();
        tsum[tid] += v;
        __syncthreads();
    }
    int excl = (tid == 0) ? 0 : tsum[tid - 1];
    for (int i = lo; i < hi; i++) {
        int c = g_cnt[i];
        g_row[i] = excl;
        g_cur[i] = excl;
        excl += c;
    }
    if (tid == 1023) g_row[N_NODES] = tsum[1023];
}

__global__ void csr_fill(const void* __restrict__ eiv) {
    int e = blockIdx.x * blockDim.x + threadIdx.x;
    if (e >= N_EDGES) return;
    int src, dst;
    if (g_is64) {
        const long long* ei = (const long long*)eiv;
        src = (int)ei[e]; dst = (int)ei[N_EDGES + e];
    } else {
        const int* ei = (const int*)eiv;
        src = ei[e]; dst = ei[N_EDGES + e];
    }
    if ((unsigned)src >= N_NODES || (unsigned)dst >= N_NODES) return;
    int pos = atomicAdd(&g_cur[dst], 1);
    g_csr[pos] = src;
}

// ---------------- HMMA GEMM: R11 structure, fp16 in/out, K=224 ----------------
#define APITCH 40
#define BPITCH 136

__global__ __launch_bounds__(256) void gemm_mma(
    const __half* __restrict__ A,
    const __half* __restrict__ B,
    const float* __restrict__ bias,
    __half* __restrict__ C, int ldb)
{
    __shared__ __half As[2][128][APITCH];
    __shared__ __half Bs[2][32][BPITCH];
    const int tid = threadIdx.x, lane = tid & 31, wid = tid >> 5;
    const int warpM = (wid & 3) * 32, warpN = (wid >> 2) * 64;
    const int row0 = blockIdx.y * 128, col0 = blockIdx.x * 128;

    float acc[2][8][4];
#pragma unroll
    for (int i = 0; i < 2; i++)
#pragma unroll
        for (int j = 0; j < 8; j++)
#pragma unroll
            for (int q = 0; q < 4; q++) acc[i][j][q] = 0.f;

#define LOAD_STAGE(ch, buf) do { \
    int _k0 = (ch) * 32; \
    _Pragma("unroll") \
    for (int it = 0; it < 2; it++) { \
        int idx = tid + it * 256; \
        int r = idx >> 2, seg = idx & 3; \
        const void* s_ = A + (size_t)(row0 + r) * KEFF + _k0 + seg * 8; \
        CP_ASYNC16(saddr(&As[buf][r][seg * 8]), s_); \
    } \
    _Pragma("unroll") \
    for (int it = 0; it < 2; it++) { \
        int idx = tid + it * 256; \
        int r = idx >> 4, seg = idx & 15; \
        const void* s_ = B + (size_t)(_k0 + r) * ldb + col0 + seg * 8; \
        CP_ASYNC16(saddr(&Bs[buf][r][seg * 8]), s_); \
    } \
    CP_COMMIT(); \
} while (0)

    LOAD_STAGE(0, 0);

    for (int ch = 0; ch < NCH; ch++) {
        int buf = ch & 1;
        if (ch + 1 < NCH) {
            LOAD_STAGE(ch + 1, buf ^ 1);
            asm volatile("cp.async.wait_group 1;");
        } else {
            asm volatile("cp.async.wait_group 0;");
        }
        __syncthreads();

#pragma unroll
        for (int kk = 0; kk < 2; kk++) {
            uint32_t a[2][4], b[4][4];
#pragma unroll
            for (int mt = 0; mt < 2; mt++)
                ldsm4(a[mt], saddr(&As[buf][warpM + mt * 16 + (lane & 15)][kk * 16 + (lane >> 4) * 8]));
#pragma unroll
            for (int nt = 0; nt < 4; nt++)
                ldsm4t(b[nt], saddr(&Bs[buf][kk * 16 + (lane & 15)][warpN + nt * 16 + (lane >> 4) * 8]));
#pragma unroll
            for (int mt = 0; mt < 2; mt++)
#pragma unroll
                for (int n8 = 0; n8 < 8; n8++)
                    mma16816(acc[mt][n8], a[mt], b[n8 >> 1][(n8 & 1) * 2], b[n8 >> 1][(n8 & 1) * 2 + 1]);
        }
        __syncthreads();
    }

#pragma unroll
    for (int mt = 0; mt < 2; mt++) {
        int r = row0 + warpM + mt * 16 + (lane >> 2);
#pragma unroll
        for (int n8 = 0; n8 < 8; n8++) {
            int c = col0 + warpN + n8 * 8 + (lane & 3) * 2;
            float b0 = bias[c], b1 = bias[c + 1];
            __half2 v0 = __floats2half2_rn(acc[mt][n8][0] + b0, acc[mt][n8][1] + b1);
            __half2 v1 = __floats2half2_rn(acc[mt][n8][2] + b0, acc[mt][n8][3] + b1);
            *(__half2*)(C + (size_t)r * ldb + c) = v0;
            *(__half2*)(C + (size_t)(r + 8) * ldb + c) = v1;
        }
    }
#undef LOAD_STAGE
}

// ---------------- CSR segment-sum: warp-per-node over fp16 h-image ----------------
__global__ __launch_bounds__(256) void aggregate_kernel() {
    int warp = threadIdx.x >> 5, lane = threadIdx.x & 31;
    int n = blockIdx.x * 8 + warp;
    if (n >= N_NODES) return;
    int beg = g_row[n], end = g_row[n + 1];
    if (lane < NCHUNK) {
        float acc[8];
#pragma unroll
        for (int q = 0; q < 8; q++) acc[q] = 0.f;
        for (int e = beg; e < end; e++) {
            int s = g_csr[e];
            uint4 v = *(const uint4*)(g_Ah + (size_t)s * KEFF + lane * 8);
            const __half* hv = (const __half*)&v;
#pragma unroll
            for (int q = 0; q < 8; q++) acc[q] += __half2float(hv[q]);
        }
        __half out[8];
#pragma unroll
        for (int q = 0; q < 8; q++) out[q] = __float2half_rn(acc[q]);
        *(uint4*)(g_As + (size_t)n * KEFF + lane * 8) = *(uint4*)out;
    }
}

// ---------------- fused GRU: h update + next-step fp16 image ----------------
__global__ __launch_bounds__(256) void gru_kernel() {
    __shared__ float hs[8][KEFF];
    int warp = threadIdx.x >> 5, lane = threadIdx.x & 31;
    int n = blockIdx.x * 8 + warp;
    if (n >= N_NODES) return;
    size_t gb = (size_t)n * NPAD;
    size_t tb = (size_t)n * NPAD;
    for (int j = lane; j < KEFF; j += 32) {
        float hnew = 0.f;
        if (j < D) {
            float ir  = __half2float(g_gi[gb + j]);
            float iz  = __half2float(g_gi[gb + D + j]);
            float in_ = __half2float(g_gi[gb + 2 * D + j]);
            float hr  = __half2float(g_T[tb + j]);
            float hz  = __half2float(g_T[tb + D + j]);
            float hn  = __half2float(g_T[tb + 2 * D + j]);
            float r = 1.f / (1.f + expf(-(ir + hr)));
            float z = 1.f / (1.f + expf(-(iz + hz)));
            float nn = tanhf(in_ + r * hn);
            float hold = g_h[(size_t)n * D + j];
            hnew = (1.f - z) * nn + z * hold;
            g_h[(size_t)n * D + j] = hnew;
        }
        hs[warp][j] = hnew;
    }
    __syncwarp();
    for (int c = lane; c < NCHUNK; c += 32) {
        int j0 = c * 8;
        __half out[8];
#pragma unroll
        for (int q = 0; q < 8; q++) out[q] = __float2half_rn(hs[warp][j0 + q]);
        *(uint4*)(g_Ah + (size_t)n * KEFF + j0) = *(uint4*)out;
    }
}

// ---------------- global max pool + classifier ----------------
__global__ void pool_kernel() {
    int j = blockIdx.x;
    float m = -3.402823466e38f;
    for (int n = threadIdx.x; n < N_NODES; n += 256)
        m = fmaxf(m, g_h[(size_t)n * D + j]);
    __shared__ float s[256];
    s[threadIdx.x] = m;
    __syncthreads();
    for (int o = 128; o > 0; o >>= 1) {
        if (threadIdx.x < o) s[threadIdx.x] = fmaxf(s[threadIdx.x], s[threadIdx.x + o]);
        __syncthreads();
    }
    if (threadIdx.x == 0) g_pool[j] = fmaxf(s[0], 0.f);
}

__global__ void cls_kernel(const float* __restrict__ cls_w,
                           const float* __restrict__ cls_b,
                           float* __restrict__ out) {
    if (blockIdx.x == 0 && threadIdx.x == 0) {
        float l0 = cls_b[0], l1 = cls_b[1];
        for (int j = 0; j < D; j++) {
            float p = g_pool[j];
            l0 += p * cls_w[j];
            l1 += p * cls_w[D + j];
        }
        float mx = fmaxf(l0, l1);
        float e0 = expf(l0 - mx), e1 = expf(l1 - mx);
        float s = e0 + e1;
        out[0] = e0 / s;
        out[1] = e1 / s;
    }
}

// ---------------- host launcher ----------------
extern "C" void kernel_launch(void* const* d_in, const int* in_sizes, int n_in,
                              void* d_out, int out_size) {
    const float* x     = (const float*)d_in[0];
    const float* W     = (const float*)d_in[1];
    const float* w_ih  = (const float*)d_in[2];
    const float* w_hh  = (const float*)d_in[3];
    const float* b_ih  = (const float*)d_in[4];
    const float* b_hh  = (const float*)d_in[5];
    const float* cls_w = (const float*)d_in[6];
    const float* cls_b = (const float*)d_in[7];
    const void*  ei    = (const void*)d_in[8];
    float* out = (float*)d_out;

    float *bhh_p, *bih_p;
    __half *T_p, *gi_p, *Ah_p, *As_p, *Bgi_p, *Bhh_p;
    cudaGetSymbolAddress((void**)&T_p,   g_T);
    cudaGetSymbolAddress((void**)&gi_p,  g_gi);
    cudaGetSymbolAddress((void**)&Ah_p,  g_Ah);
    cudaGetSymbolAddress((void**)&As_p,  g_As);
    cudaGetSymbolAddress((void**)&Bgi_p, g_Bgi);
    cudaGetSymbolAddress((void**)&Bhh_p, g_Bhh);
    cudaGetSymbolAddress((void**)&bhh_p, g_bias_hh);
    cudaGetSymbolAddress((void**)&bih_p, g_bias_ih);

    const int TB = 256;
    const int PREP_TOTAL = NUM_STEPS * KEFF * (NPAD / 8) + KEFF * (NPAD / 8) + 2 * NPAD;

    prep_wc<<<dim3(38, 13, NUM_STEPS), 256>>>(W, w_ih);
    prep_w<<<(PREP_TOTAL + TB - 1) / TB, TB>>>(w_hh, b_hh, b_ih);
    detect_zero<<<(N_NODES + TB - 1) / TB, TB>>>((const int*)ei);
    init_fused<<<(NODES_PAD + 7) / 8, 256>>>(x);
    csr_count<<<(N_EDGES + TB - 1) / TB, TB>>>(ei);
    csr_scan<<<1, 1024>>>();
    csr_fill<<<(N_EDGES + TB - 1) / TB, TB>>>(ei);

    dim3 grid(NT, M_TILES);
    for (int s = 0; s < NUM_STEPS; s++) {
        aggregate_kernel<<<(N_NODES + 7) / 8, 256>>>();
        gemm_mma<<<grid, 256>>>(Ah_p, Bhh_p, bhh_p, T_p, NPAD);
        gemm_mma<<<grid, 256>>>(As_p, Bgi_p + (size_t)s * KEFF * NPAD, bih_p, gi_p, NPAD);
        gru_kernel<<<(N_NODES + 7) / 8, 256>>>();
    }

    pool_kernel<<<D, 256>>>();
    cls_kernel<<<1, 32>>>(cls_w, cls_b, out);
}